// round 16
// baseline (speedup 1.0000x reference)
#include <cuda_runtime.h>
#include <cuda_bf16.h>
#include <math.h>

#define BB   16
#define KC   64
#define WW   2048
#define LL   2112
#define DD   512
#define DHH  256
#define DFFF 2048
#define NLL  4
#define LN_EPS 1e-5f

typedef __nv_bfloat16 bf16;

// ---------------------------------------------------------------------------
// Device scratch (statics; no allocations allowed)
// ---------------------------------------------------------------------------
__device__ float g_h [(long)BB*LL*DD];          // residual (fp32)
__device__ float g_s [(long)BB*LL*WW];          // seq scores fp32   (A chain)
__device__ float g_sc[(long)BB*LL*KC];          // cache scores fp32 (B chain)
__device__ bf16 g_hn2 [(long)BB*LL*2*DD];       // LN out   [hi|lo]
__device__ bf16 g_q2  [(long)BB*LL*2*DHH];      // Q seq    [hi|lo]
__device__ bf16 g_qb2 [(long)BB*LL*2*DHH];      // Q cache  [hi|lo]  (B chain)
__device__ bf16 g_k2  [(long)BB*WW*2*DHH];      // K seq    [hi|lo]
__device__ bf16 g_v2  [(long)BB*2*WW*DHH];      // V seq    [hi;lo] stacked
__device__ bf16 g_kc2 [(long)BB*KC*2*DHH];      // K cache
__device__ bf16 g_vc2 [(long)BB*2*KC*DHH];      // V cache stacked
__device__ bf16 g_p2  [(long)BB*LL*2*WW];       // P seq / FFN mid [hi|lo]
__device__ bf16 g_pc2 [(long)BB*LL*2*KC];       // P cache [hi|lo]
__device__ bf16 g_cat2[(long)BB*LL*2*DD];       // concat attn out [hi|lo]
#define WL 6291456L                              // split weights per layer (elements)
__device__ bf16 g_w2  [4*WL];
// per-layer offsets inside g_w2
#define OQ  0L
#define OK_ 262144L
#define OV  524288L
#define OQC 786432L
#define OKCo 1048576L
#define OVC 1310720L
#define OWO 1572864L
#define OF1 2097152L
#define OF2 4194304L

#define FLAG_RES  1
#define FLAG_RELU 2

// ---------------------------------------------------------------------------
// Elementwise kernels
// ---------------------------------------------------------------------------
__global__ void embed_kernel(const int* __restrict__ cache, const int* __restrict__ seq,
                             const float* __restrict__ item, const float* __restrict__ cpos,
                             const float* __restrict__ spos, const float* __restrict__ seg,
                             float* __restrict__ h) {
    int r = blockIdx.x;
    int b = r / LL, l = r % LL;
    int idx; const float* pos; const float* sg;
    if (l < KC) { idx = cache[b * KC + l]; pos = cpos + (long)l * DD; sg = seg; }
    else        { int i = l - KC; idx = seq[b * WW + i]; pos = spos + (long)i * DD; sg = seg + DD; }
    const float* it = item + (long)idx * DD;
    float* hr = h + (long)r * DD;
    for (int d = threadIdx.x; d < DD; d += blockDim.x)
        hr[d] = it[d] + pos[d] + sg[d];
}

// split fp32 -> (hi, lo) bf16
__global__ void split_kernel(const float* __restrict__ src, bf16* __restrict__ hi,
                             bf16* __restrict__ lo, long n) {
    long i = blockIdx.x * 256L + threadIdx.x;
    if (i < n) {
        float v = src[i];
        bf16 hh = __float2bfloat16_rn(v);
        hi[i] = hh;
        lo[i] = __float2bfloat16_rn(v - __bfloat162float(hh));
    }
}

// LayerNorm, split output row [hi(0..D-1) | lo(D..2D-1)], stride 2D
__global__ void ln_split_kernel(const float* __restrict__ x, bf16* __restrict__ y,
                                const float* __restrict__ g, const float* __restrict__ bia) {
    __shared__ float rs[256], rq[256];
    long row = (long)blockIdx.y * LL + blockIdx.x;
    const float* xr = x + row * DD;
    bf16* yr = y + row * (2 * DD);
    int t = threadIdx.x;
    float v0 = xr[t], v1 = xr[t + 256];
    rs[t] = v0 + v1; rq[t] = v0 * v0 + v1 * v1; __syncthreads();
    for (int o = 128; o > 0; o >>= 1) {
        if (t < o) { rs[t] += rs[t + o]; rq[t] += rq[t + o]; }
        __syncthreads();
    }
    float mean = rs[0] * (1.0f / DD);
    float inv  = rsqrtf(rq[0] * (1.0f / DD) - mean * mean + LN_EPS);
    float o0 = (v0 - mean) * inv * g[t]       + bia[t];
    float o1 = (v1 - mean) * inv * g[t + 256] + bia[t + 256];
    bf16 h0 = __float2bfloat16_rn(o0), h1 = __float2bfloat16_rn(o1);
    yr[t]            = h0;
    yr[t + 256]      = h1;
    yr[DD + t]       = __float2bfloat16_rn(o0 - __bfloat162float(h0));
    yr[DD + t + 256] = __float2bfloat16_rn(o1 - __bfloat162float(h1));
}

// Single-pass seq softmax: 512 threads, 4 cols each (W=2048). Reads are guarded
// (skipped score tiles hold garbage); masked tail written as exact zeros.
__global__ void softmax_seq_kernel(const float* __restrict__ S, bf16* __restrict__ P) {
    __shared__ float red[512];
    int l = blockIdx.x, b = blockIdx.y;
    const float* p = S + ((long)b * LL + l) * WW;
    bf16* d = P + ((long)b * LL + l) * (2 * WW);
    int valid = (l < KC) ? WW : (l - KC + 1);
    int t = threadIdx.x;

    float v[4];
    float m = -1e30f;
#pragma unroll
    for (int j = 0; j < 4; j++) {
        int col = t + j * 512;
        v[j] = (col < valid) ? p[col] : -1e30f;
        m = fmaxf(m, v[j]);
    }
    red[t] = m; __syncthreads();
    for (int o = 256; o > 0; o >>= 1) { if (t < o) red[t] = fmaxf(red[t], red[t + o]); __syncthreads(); }
    m = red[0]; __syncthreads();

    float s = 0.f;
#pragma unroll
    for (int j = 0; j < 4; j++) { float e = expf(v[j] - m); v[j] = e; s += e; }
    red[t] = s; __syncthreads();
    for (int o = 256; o > 0; o >>= 1) { if (t < o) red[t] += red[t + o]; __syncthreads(); }
    float inv = 1.0f / red[0];

#pragma unroll
    for (int j = 0; j < 4; j++) {
        int col = t + j * 512;
        float val = (col < valid) ? v[j] * inv : 0.f;
        bf16 hh = __float2bfloat16_rn(val);
        d[col]      = hh;
        d[WW + col] = __float2bfloat16_rn(val - __bfloat162float(hh));
    }
}

// Cache softmax: 64 threads, 1 col each, no mask.
__global__ void softmax_cache_kernel(const float* __restrict__ S, bf16* __restrict__ P) {
    __shared__ float red[64];
    int l = blockIdx.x, b = blockIdx.y;
    const float* p = S + ((long)b * LL + l) * KC;
    bf16* d = P + ((long)b * LL + l) * (2 * KC);
    int t = threadIdx.x;
    float v = p[t];
    red[t] = v; __syncthreads();
    for (int o = 32; o > 0; o >>= 1) { if (t < o) red[t] = fmaxf(red[t], red[t + o]); __syncthreads(); }
    float m = red[0]; __syncthreads();
    float e = expf(v - m);
    red[t] = e; __syncthreads();
    for (int o = 32; o > 0; o >>= 1) { if (t < o) red[t] += red[t + o]; __syncthreads(); }
    float val = e / red[0];
    bf16 hh = __float2bfloat16_rn(val);
    d[t]      = hh;
    d[KC + t] = __float2bfloat16_rn(val - __bfloat162float(hh));
}

__global__ void final_kernel(const float* __restrict__ h, const float* __restrict__ fg,
                             const float* __restrict__ fb, const float* __restrict__ wev,
                             const float* __restrict__ bev, float* __restrict__ out) {
    __shared__ float rs[256], rq[256];
    int l = blockIdx.x, b = blockIdx.y;
    const float* xr = h + ((long)b * LL + l) * DD;
    int t = threadIdx.x;
    float v0 = xr[t], v1 = xr[t + 256];
    rs[t] = v0 + v1; rq[t] = v0 * v0 + v1 * v1; __syncthreads();
    for (int o = 128; o > 0; o >>= 1) {
        if (t < o) { rs[t] += rs[t + o]; rq[t] += rq[t + o]; }
        __syncthreads();
    }
    float mean = rs[0] * (1.0f / DD);
    float inv  = rsqrtf(rq[0] * (1.0f / DD) - mean * mean + LN_EPS);
    __syncthreads();
    float d0 = ((v0 - mean) * inv * fg[t]       + fb[t])       * wev[t];
    float d1 = ((v1 - mean) * inv * fg[t + 256] + fb[t + 256]) * wev[t + 256];
    rs[t] = d0 + d1; __syncthreads();
    for (int o = 128; o > 0; o >>= 1) { if (t < o) rs[t] += rs[t + o]; __syncthreads(); }
    if (t == 0) out[b * KC + l] = rs[0] + bev[0];
}

// ---------------------------------------------------------------------------
// bf16x3 GEMM via 3 virtual K-segments over pre-split operands.
// A: (M x 2*KH) [hi|lo] row-major. B:
//   BSTYLE 0: (2*KH x N)  k-major [hi;lo] stacked rows
//   BSTYLE 1: (N x 2*KH)  [hi|lo] row-major (B^T)
// causalKC >= 0: BSTYLE 1 -> skip fully-masked 128x128 score tiles;
//                BSTYLE 0 -> truncate k-loop at the causal diagonal.
// Block 128x128, 8 warps (2x4), warp 64x32, mma m16n8k16 bf16, fp32 accum.
// cp.async 4-stage pipeline, ONE __syncthreads per k-tile.
// ---------------------------------------------------------------------------
__device__ __forceinline__ void mma_bf16(float* c, const unsigned* a, const unsigned* b) {
    asm volatile(
        "mma.sync.aligned.m16n8k16.row.col.f32.bf16.bf16.f32 "
        "{%0,%1,%2,%3}, {%4,%5,%6,%7}, {%8,%9}, {%0,%1,%2,%3};"
        : "+f"(c[0]), "+f"(c[1]), "+f"(c[2]), "+f"(c[3])
        : "r"(a[0]), "r"(a[1]), "r"(a[2]), "r"(a[3]), "r"(b[0]), "r"(b[1]));
}

__device__ __forceinline__ void cpasync16(unsigned daddr, const void* src) {
    asm volatile("cp.async.cg.shared.global [%0], [%1], 16;" :: "r"(daddr), "l"(src));
}

#define ST_BYTES 10240
#define NSTAGE   4

template <int BSTYLE>
__global__ __launch_bounds__(256)
void gemm3(const bf16* __restrict__ A, int lda, long sA,
           const bf16* __restrict__ B, int ldb, long sB,
           int M, int N, int KH, int causalKC,
           float* Cf, int ldcf, long sCf,
           bf16* Chi, bf16* Clo, int ldc2, long sC2,
           const float* __restrict__ bias, float alpha, int flags) {
    const int m0 = blockIdx.y * 128, n0 = blockIdx.x * 128;

    if (BSTYLE == 1 && causalKC >= 0 && m0 >= causalKC && n0 > m0 + 127 - causalKC)
        return;  // fully masked score tile

    int KHlim = KH;
    if (BSTYLE == 0 && causalKC >= 0 && m0 >= causalKC)
        KHlim = min(KH, m0 + 128 - causalKC);   // multiple of 32

    extern __shared__ __align__(16) unsigned char smraw[];
    unsigned aS = (unsigned)__cvta_generic_to_shared(smraw);
    unsigned bS = aS + NSTAGE * ST_BYTES;

    A += (long)blockIdx.z * sA;
    B += (long)blockIdx.z * sB;
    if (Cf)  Cf  += (long)blockIdx.z * sCf;
    if (Chi) { Chi += (long)blockIdx.z * sC2; Clo += (long)blockIdx.z * sC2; }

    const int tid  = threadIdx.x;
    const int lane = tid & 31;
    const int warp = tid >> 5;
    const int wm = (warp >> 2) * 64;
    const int wn = (warp & 3) * 32;
    const int r = lane >> 2, c = lane & 3;

    float acc[4][4][4] = {{{0.f}}};

    const int segs = KHlim >> 5;
    const int KT = segs * 3;

    auto stage = [&](int st, int kt) {
        int sgi = (kt >= segs) + (kt >= 2 * segs);
        int ko = (kt - sgi * segs) << 5;
        int ao = ko + (sgi == 1 ? KH : 0);
        int bo = ko + (sgi == 2 ? KH : 0);
        unsigned ab = aS + st * ST_BYTES;
        unsigned bb = bS + st * ST_BYTES;
        int ch = tid * 2;
#pragma unroll
        for (int i = 0; i < 2; i++) {
            int cc2 = ch + i;
            int row = cc2 >> 2, c16 = cc2 & 3;
            const bf16* src = A + (long)min(m0 + row, M - 1) * lda + ao + c16 * 8;
            cpasync16(ab + row * 80 + c16 * 16, src);
        }
        if (BSTYLE == 1) {
#pragma unroll
            for (int i = 0; i < 2; i++) {
                int cc2 = ch + i;
                int row = cc2 >> 2, c16 = cc2 & 3;
                const bf16* src = B + (long)min(n0 + row, N - 1) * ldb + bo + c16 * 8;
                cpasync16(bb + row * 80 + c16 * 16, src);
            }
        } else {
#pragma unroll
            for (int i = 0; i < 2; i++) {
                int cc2 = ch + i;
                int row = cc2 >> 4, c16 = cc2 & 15;
                int col = min(n0 + c16 * 8, N - 8);
                const bf16* src = B + (long)(bo + row) * ldb + col;
                cpasync16(bb + row * 272 + c16 * 16, src);
            }
        }
    };

    // prologue: 3 stages in flight
    stage(0, 0);
    asm volatile("cp.async.commit_group;");
    if (KT > 1) stage(1, 1);
    asm volatile("cp.async.commit_group;");
    if (KT > 2) stage(2, 2);
    asm volatile("cp.async.commit_group;");

    for (int kt = 0; kt < KT; kt++) {
        asm volatile("cp.async.wait_group 2;");
        __syncthreads();                 // stage kt visible; buffer kt%4 safe to refill
        if (kt + 3 < KT) stage((kt + 3) & (NSTAGE - 1), kt + 3);
        asm volatile("cp.async.commit_group;");

        const int st = kt & (NSTAGE - 1);
        const unsigned ab = aS + st * ST_BYTES;
        const unsigned bb = bS + st * ST_BYTES;
#pragma unroll
        for (int kh = 0; kh < 2; kh++) {
            unsigned a[4][4];
#pragma unroll
            for (int mf = 0; mf < 4; mf++) {
                int row = wm + mf * 16 + (lane & 15);
                unsigned ad = ab + row * 80 + (kh * 2 + (lane >> 4)) * 16;
                asm volatile("ldmatrix.sync.aligned.m8n8.x4.shared.b16 {%0,%1,%2,%3}, [%4];"
                             : "=r"(a[mf][0]), "=r"(a[mf][1]), "=r"(a[mf][2]), "=r"(a[mf][3])
                             : "r"(ad));
            }
            unsigned bfr[4][2];
#pragma unroll
            for (int nfp = 0; nfp < 2; nfp++) {
                int g = lane >> 3, rr2 = lane & 7;
                if (BSTYLE == 1) {
                    int row = wn + nfp * 16 + ((g >> 1) & 1) * 8 + rr2;
                    unsigned ad = bb + row * 80 + (kh * 2 + (g & 1)) * 16;
                    asm volatile("ldmatrix.sync.aligned.m8n8.x4.shared.b16 {%0,%1,%2,%3}, [%4];"
                                 : "=r"(bfr[nfp*2][0]), "=r"(bfr[nfp*2][1]),
                                   "=r"(bfr[nfp*2+1][0]), "=r"(bfr[nfp*2+1][1])
                                 : "r"(ad));
                } else {
                    int row = kh * 16 + (g & 1) * 8 + rr2;
                    int c16 = ((wn + nfp * 16) >> 3) + ((g >> 1) & 1);
                    unsigned ad = bb + row * 272 + c16 * 16;
                    asm volatile("ldmatrix.sync.aligned.m8n8.x4.trans.shared.b16 {%0,%1,%2,%3}, [%4];"
                                 : "=r"(bfr[nfp*2][0]), "=r"(bfr[nfp*2][1]),
                                   "=r"(bfr[nfp*2+1][0]), "=r"(bfr[nfp*2+1][1])
                                 : "r"(ad));
                }
            }
#pragma unroll
            for (int mf = 0; mf < 4; mf++)
#pragma unroll
                for (int nf = 0; nf < 4; nf++)
                    mma_bf16(acc[mf][nf], a[mf], bfr[nf]);
        }
    }

    // ---- epilogue ----
#pragma unroll
    for (int mf = 0; mf < 4; mf++) {
        int r0 = m0 + wm + mf * 16 + r;
#pragma unroll
        for (int nf = 0; nf < 4; nf++) {
            int cc = n0 + wn + nf * 8 + c * 2;
            if (cc < N) {
#pragma unroll
                for (int half = 0; half < 2; half++) {
                    int rr = r0 + half * 8;
                    if (rr < M) {
                        float v0 = alpha * acc[mf][nf][half * 2 + 0];
                        float v1 = alpha * acc[mf][nf][half * 2 + 1];
                        if (bias) { v0 += bias[cc]; v1 += bias[cc + 1]; }
                        if (flags & FLAG_RELU) { v0 = fmaxf(v0, 0.f); v1 = fmaxf(v1, 0.f); }
                        if (Cf) {
                            long base = (long)rr * ldcf + cc;
                            float w0 = v0, w1 = v1;
                            if (flags & FLAG_RES) { w0 += Cf[base]; w1 += Cf[base + 1]; }
                            Cf[base] = w0; Cf[base + 1] = w1;
                        }
                        if (Chi) {
                            long base = (long)rr * ldc2 + cc;
                            bf16 h0 = __float2bfloat16_rn(v0);
                            bf16 h1 = __float2bfloat16_rn(v1);
                            Chi[base]     = h0;
                            Chi[base + 1] = h1;
                            Clo[base]     = __float2bfloat16_rn(v0 - __bfloat162float(h0));
                            Clo[base + 1] = __float2bfloat16_rn(v1 - __bfloat162float(h1));
                        }
                    }
                }
            }
        }
    }
}

// ---------------------------------------------------------------------------
// Host launcher
// ---------------------------------------------------------------------------
static void G3(int bstyle, const bf16* A, int lda, long sA,
               const bf16* B, int ldb, long sB,
               int M, int N, int KH, int causalKC,
               float* Cf, int ldcf, long sCf,
               bf16* Chi, bf16* Clo, int ldc2, long sC2,
               const float* bias, float alpha, int flags, cudaStream_t st) {
    dim3 grid((N + 127) / 128, (M + 127) / 128, BB);
    size_t sh = 2 * NSTAGE * ST_BYTES;
    if (bstyle)
        gemm3<1><<<grid, 256, sh, st>>>(A, lda, sA, B, ldb, sB, M, N, KH, causalKC,
                                        Cf, ldcf, sCf, Chi, Clo, ldc2, sC2, bias, alpha, flags);
    else
        gemm3<0><<<grid, 256, sh, st>>>(A, lda, sA, B, ldb, sB, M, N, KH, causalKC,
                                        Cf, ldcf, sCf, Chi, Clo, ldc2, sC2, bias, alpha, flags);
}

extern "C" void kernel_launch(void* const* d_in, const int* in_sizes, int n_in,
                              void* d_out, int out_size) {
    const int*   cache = (const int*)d_in[0];
    const int*   seq   = (const int*)d_in[1];
    const float* item  = (const float*)d_in[2];
    const float* cpos  = (const float*)d_in[3];
    const float* spos  = (const float*)d_in[4];
    const float* seg   = (const float*)d_in[5];
    const float* wq_s  = (const float*)d_in[6];
    const float* wk_s  = (const float*)d_in[7];
    const float* wv_s  = (const float*)d_in[8];
    const float* wq_c  = (const float*)d_in[9];
    const float* wk_c  = (const float*)d_in[10];
    const float* wv_c  = (const float*)d_in[11];
    const float* w_out = (const float*)d_in[12];
    const float* b_out = (const float*)d_in[13];
    const float* ln1g  = (const float*)d_in[14];
    const float* ln1b  = (const float*)d_in[15];
    const float* ln2g  = (const float*)d_in[16];
    const float* ln2b  = (const float*)d_in[17];
    const float* wff1  = (const float*)d_in[18];
    const float* bff1  = (const float*)d_in[19];
    const float* wff2  = (const float*)d_in[20];
    const float* bff2  = (const float*)d_in[21];
    const float* fing  = (const float*)d_in[22];
    const float* finb  = (const float*)d_in[23];
    const float* wev   = (const float*)d_in[24];
    const float* bev   = (const float*)d_in[25];
    float* out = (float*)d_out;

    cudaFuncSetAttribute(gemm3<0>, cudaFuncAttributeMaxDynamicSharedMemorySize, 2 * NSTAGE * ST_BYTES);
    cudaFuncSetAttribute(gemm3<1>, cudaFuncAttributeMaxDynamicSharedMemorySize, 2 * NSTAGE * ST_BYTES);

    float *h, *s, *sc;
    bf16 *hn2, *q2, *qb2, *k2, *v2, *kc2, *vc2, *p2, *pc2, *cat2, *w2;
    cudaGetSymbolAddress((void**)&h,   g_h);
    cudaGetSymbolAddress((void**)&s,   g_s);
    cudaGetSymbolAddress((void**)&sc,  g_sc);
    cudaGetSymbolAddress((void**)&hn2, g_hn2);
    cudaGetSymbolAddress((void**)&q2,  g_q2);
    cudaGetSymbolAddress((void**)&qb2, g_qb2);
    cudaGetSymbolAddress((void**)&k2,  g_k2);
    cudaGetSymbolAddress((void**)&v2,  g_v2);
    cudaGetSymbolAddress((void**)&kc2, g_kc2);
    cudaGetSymbolAddress((void**)&vc2, g_vc2);
    cudaGetSymbolAddress((void**)&p2,  g_p2);
    cudaGetSymbolAddress((void**)&pc2, g_pc2);
    cudaGetSymbolAddress((void**)&cat2,g_cat2);
    cudaGetSymbolAddress((void**)&w2,  g_w2);

    const float scale = 0.0625f;   // 1/sqrt(256)

    // ---- fork/join resources (created+destroyed per call; no device memory) ----
    cudaStream_t s2;
    cudaStreamCreateWithFlags(&s2, cudaStreamNonBlocking);
    cudaEvent_t evF[NLL], evB[NLL];
    for (int i = 0; i < NLL; i++) {
        cudaEventCreateWithFlags(&evF[i], cudaEventDisableTiming);
        cudaEventCreateWithFlags(&evB[i], cudaEventDisableTiming);
    }

    // ---- split all weights (stacked [hi;lo]) on main stream ----
    for (int l = 0; l < NLL; l++) {
        bf16* wb = w2 + l * WL;
        auto SPL = [&](const float* src, bf16* dst, long els) {
            split_kernel<<<(unsigned)((els + 255) / 256), 256>>>(src, dst, dst + els, els);
        };
        SPL(wq_s + (long)l * DD * DHH,  wb + OQ,   (long)DD * DHH);
        SPL(wk_s + (long)l * DD * DHH,  wb + OK_,  (long)DD * DHH);
        SPL(wv_s + (long)l * DD * DHH,  wb + OV,   (long)DD * DHH);
        SPL(wq_c + (long)l * DD * DHH,  wb + OQC,  (long)DD * DHH);
        SPL(wk_c + (long)l * DD * DHH,  wb + OKCo, (long)DD * DHH);
        SPL(wv_c + (long)l * DD * DHH,  wb + OVC,  (long)DD * DHH);
        SPL(w_out + (long)l * DD * DD,  wb + OWO,  (long)DD * DD);
        SPL(wff1 + (long)l * DD * DFFF, wb + OF1,  (long)DD * DFFF);
        SPL(wff2 + (long)l * DFFF * DD, wb + OF2,  (long)DFFF * DD);
    }

    embed_kernel<<<BB * LL, 256>>>(cache, seq, item, cpos, spos, seg, h);

    for (int l = 0; l < NLL; l++) {
        bf16* wb = w2 + l * WL;
        const float* Bo = b_out + (long)l * DD;
        const float* B1 = bff1 + (long)l * DFFF;
        const float* B2 = bff2 + (long)l * DD;

        const int Mq = (l == NLL - 1) ? KC : LL;

        // ---- LN1 (all rows) on main ----
        ln_split_kernel<<<dim3(LL, BB), 256>>>(h, hn2, ln1g + l * DD, ln1b + l * DD);

        // ---- fork: B chain depends only on hn2 ----
        cudaEventRecord(evF[l], 0);
        cudaStreamWaitEvent(s2, evF[l], 0);

        // ======== A chain (main stream): seq attention ========
        G3(0, hn2, 2*DD, (long)LL*2*DD, wb + OQ, DHH, 0, Mq, DHH, DD, -1,
           0, 0, 0, q2, q2 + DHH, 2*DHH, (long)LL*2*DHH, 0, 1.f, 0, 0);
        G3(0, hn2 + (long)KC*2*DD, 2*DD, (long)LL*2*DD, wb + OK_, DHH, 0, WW, DHH, DD, -1,
           0, 0, 0, k2, k2 + DHH, 2*DHH, (long)WW*2*DHH, 0, 1.f, 0, 0);
        G3(0, hn2 + (long)KC*2*DD, 2*DD, (long)LL*2*DD, wb + OV, DHH, 0, WW, DHH, DD, -1,
           0, 0, 0, v2, v2 + (long)WW*DHH, DHH, (long)2*WW*DHH, 0, 1.f, 0, 0);
        G3(1, q2, 2*DHH, (long)LL*2*DHH, k2, 2*DHH, (long)WW*2*DHH, Mq, WW, DHH, KC,
           s, WW, (long)LL*WW, 0, 0, 0, 0, 0, scale, 0, 0);
        softmax_seq_kernel<<<dim3(Mq, BB), 512>>>(s, p2);
        G3(0, p2, 2*WW, (long)LL*2*WW, v2, DHH, (long)2*WW*DHH, Mq, DHH, WW, KC,
           0, 0, 0, cat2, cat2 + DD, 2*DD, (long)LL*2*DD, 0, 1.f, 0, 0);

        // ======== B chain (stream s2): cache attention ========
        G3(0, hn2, 2*DD, (long)LL*2*DD, wb + OQC, DHH, 0, Mq, DHH, DD, -1,
           0, 0, 0, qb2, qb2 + DHH, 2*DHH, (long)LL*2*DHH, 0, 1.f, 0, s2);
        G3(0, hn2, 2*DD, (long)LL*2*DD, wb + OKCo, DHH, 0, KC, DHH, DD, -1,
           0, 0, 0, kc2, kc2 + DHH, 2*DHH, (long)KC*2*DHH, 0, 1.f, 0, s2);
        G3(0, hn2, 2*DD, (long)LL*2*DD, wb + OVC, DHH, 0, KC, DHH, DD, -1,
           0, 0, 0, vc2, vc2 + (long)KC*DHH, DHH, (long)2*KC*DHH, 0, 1.f, 0, s2);
        G3(1, qb2, 2*DHH, (long)LL*2*DHH, kc2, 2*DHH, (long)KC*2*DHH, Mq, KC, DHH, -1,
           sc, KC, (long)LL*KC, 0, 0, 0, 0, 0, scale, 0, s2);
        softmax_cache_kernel<<<dim3(Mq, BB), 64, 0, s2>>>(sc, pc2);
        G3(0, pc2, 2*KC, (long)LL*2*KC, vc2, DHH, (long)2*KC*DHH, Mq, DHH, KC, -1,
           0, 0, 0, cat2 + DHH, cat2 + DD + DHH, 2*DD, (long)LL*2*DD, 0, 1.f, 0, s2);

        // ---- join: WO needs both halves of cat2 ----
        cudaEventRecord(evB[l], s2);
        cudaStreamWaitEvent(0, evB[l], 0);

        // ---- Output projection + residual ----
        G3(0, cat2, 2*DD, (long)LL*2*DD, wb + OWO, DD, 0, Mq, DD, DD, -1,
           h, DD, (long)LL*DD, 0, 0, 0, 0, Bo, 1.f, FLAG_RES, 0);

        // ---- FFN ----
        ln_split_kernel<<<dim3(Mq, BB), 256>>>(h, hn2, ln2g + l * DD, ln2b + l * DD);
        G3(0, hn2, 2*DD, (long)LL*2*DD, wb + OF1, DFFF, 0, Mq, DFFF, DD, -1,
           0, 0, 0, p2, p2 + DFFF, 2*DFFF, (long)LL*2*DFFF, B1, 1.f, FLAG_RELU, 0);
        G3(0, p2, 2*DFFF, (long)LL*2*DFFF, wb + OF2, DD, 0, Mq, DD, DFFF, -1,
           h, DD, (long)LL*DD, 0, 0, 0, 0, B2, 1.f, FLAG_RES, 0);
    }

    final_kernel<<<dim3(KC, BB), 256>>>(h, fing, finb, wev, bev, out);

    for (int i = 0; i < NLL; i++) {
        cudaEventDestroy(evF[i]);
        cudaEventDestroy(evB[i]);
    }
    cudaStreamDestroy(s2);
}

// round 17
// speedup vs baseline: 1.4526x; 1.4526x over previous
#include <cuda_runtime.h>
#include <cuda_bf16.h>
#include <math.h>

#define BB   16
#define KC   64
#define WW   2048
#define LL   2112
#define DD   512
#define DHH  256
#define DFFF 2048
#define NLL  4
#define LN_EPS 1e-5f

typedef __nv_bfloat16 bf16;

// ---------------------------------------------------------------------------
// Device scratch (statics; no allocations allowed)
// ---------------------------------------------------------------------------
__device__ float g_h [(long)BB*LL*DD];          // residual (fp32)
__device__ float g_s [(long)BB*LL*WW];          // scores fp32
__device__ bf16 g_hn2 [(long)BB*LL*2*DD];       // LN out   [hi|lo]
__device__ bf16 g_q2  [(long)BB*LL*2*DHH];      // Q        [hi|lo]
__device__ bf16 g_k2  [(long)BB*WW*2*DHH];      // K seq    [hi|lo]
__device__ bf16 g_v2  [(long)BB*2*WW*DHH];      // V seq    [hi;lo] stacked
__device__ bf16 g_kc2 [(long)BB*KC*2*DHH];      // K cache
__device__ bf16 g_vc2 [(long)BB*2*KC*DHH];      // V cache stacked
__device__ bf16 g_p2  [(long)BB*LL*2*WW];       // P seq / FFN mid [hi|lo]
__device__ bf16 g_pc2 [(long)BB*LL*2*KC];       // P cache [hi|lo]
__device__ bf16 g_cat2[(long)BB*LL*2*DD];       // concat attn out [hi|lo]
#define WL 6291456L                              // split weights per layer (elements)
__device__ bf16 g_w2  [4*WL];
// per-layer offsets inside g_w2
#define OQ  0L
#define OK_ 262144L
#define OV  524288L
#define OQC 786432L
#define OKCo 1048576L
#define OVC 1310720L
#define OWO 1572864L
#define OF1 2097152L
#define OF2 4194304L

#define FLAG_RES  1
#define FLAG_RELU 2

// ---------------------------------------------------------------------------
// Elementwise kernels
// ---------------------------------------------------------------------------
__global__ void embed_kernel(const int* __restrict__ cache, const int* __restrict__ seq,
                             const float* __restrict__ item, const float* __restrict__ cpos,
                             const float* __restrict__ spos, const float* __restrict__ seg,
                             float* __restrict__ h) {
    int r = blockIdx.x;
    int b = r / LL, l = r % LL;
    int idx; const float* pos; const float* sg;
    if (l < KC) { idx = cache[b * KC + l]; pos = cpos + (long)l * DD; sg = seg; }
    else        { int i = l - KC; idx = seq[b * WW + i]; pos = spos + (long)i * DD; sg = seg + DD; }
    const float* it = item + (long)idx * DD;
    float* hr = h + (long)r * DD;
    for (int d = threadIdx.x; d < DD; d += blockDim.x)
        hr[d] = it[d] + pos[d] + sg[d];
}

// split fp32 -> (hi, lo) bf16
__global__ void split_kernel(const float* __restrict__ src, bf16* __restrict__ hi,
                             bf16* __restrict__ lo, long n) {
    long i = blockIdx.x * 256L + threadIdx.x;
    if (i < n) {
        float v = src[i];
        bf16 hh = __float2bfloat16_rn(v);
        hi[i] = hh;
        lo[i] = __float2bfloat16_rn(v - __bfloat162float(hh));
    }
}

// LayerNorm, split output row [hi(0..D-1) | lo(D..2D-1)], stride 2D
__global__ void ln_split_kernel(const float* __restrict__ x, bf16* __restrict__ y,
                                const float* __restrict__ g, const float* __restrict__ bia) {
    __shared__ float rs[256], rq[256];
    long row = (long)blockIdx.y * LL + blockIdx.x;
    const float* xr = x + row * DD;
    bf16* yr = y + row * (2 * DD);
    int t = threadIdx.x;
    float v0 = xr[t], v1 = xr[t + 256];
    rs[t] = v0 + v1; rq[t] = v0 * v0 + v1 * v1; __syncthreads();
    for (int o = 128; o > 0; o >>= 1) {
        if (t < o) { rs[t] += rs[t + o]; rq[t] += rq[t + o]; }
        __syncthreads();
    }
    float mean = rs[0] * (1.0f / DD);
    float inv  = rsqrtf(rq[0] * (1.0f / DD) - mean * mean + LN_EPS);
    float o0 = (v0 - mean) * inv * g[t]       + bia[t];
    float o1 = (v1 - mean) * inv * g[t + 256] + bia[t + 256];
    bf16 h0 = __float2bfloat16_rn(o0), h1 = __float2bfloat16_rn(o1);
    yr[t]            = h0;
    yr[t + 256]      = h1;
    yr[DD + t]       = __float2bfloat16_rn(o0 - __bfloat162float(h0));
    yr[DD + t + 256] = __float2bfloat16_rn(o1 - __bfloat162float(h1));
}

// Single-pass seq softmax: 512 threads, 4 cols each (W=2048). Reads are guarded
// (skipped score tiles hold garbage); masked tail written as exact zeros.
__global__ void softmax_seq_kernel(const float* __restrict__ S, bf16* __restrict__ P) {
    __shared__ float red[512];
    int l = blockIdx.x, b = blockIdx.y;
    const float* p = S + ((long)b * LL + l) * WW;
    bf16* d = P + ((long)b * LL + l) * (2 * WW);
    int valid = (l < KC) ? WW : (l - KC + 1);
    int t = threadIdx.x;

    float v[4];
    float m = -1e30f;
#pragma unroll
    for (int j = 0; j < 4; j++) {
        int col = t + j * 512;
        v[j] = (col < valid) ? p[col] : -1e30f;
        m = fmaxf(m, v[j]);
    }
    red[t] = m; __syncthreads();
    for (int o = 256; o > 0; o >>= 1) { if (t < o) red[t] = fmaxf(red[t], red[t + o]); __syncthreads(); }
    m = red[0]; __syncthreads();

    float s = 0.f;
#pragma unroll
    for (int j = 0; j < 4; j++) { float e = expf(v[j] - m); v[j] = e; s += e; }
    red[t] = s; __syncthreads();
    for (int o = 256; o > 0; o >>= 1) { if (t < o) red[t] += red[t + o]; __syncthreads(); }
    float inv = 1.0f / red[0];

#pragma unroll
    for (int j = 0; j < 4; j++) {
        int col = t + j * 512;
        float val = (col < valid) ? v[j] * inv : 0.f;
        bf16 hh = __float2bfloat16_rn(val);
        d[col]      = hh;
        d[WW + col] = __float2bfloat16_rn(val - __bfloat162float(hh));
    }
}

// Cache softmax: 64 threads, 1 col each, no mask.
__global__ void softmax_cache_kernel(const float* __restrict__ S, bf16* __restrict__ P) {
    __shared__ float red[64];
    int l = blockIdx.x, b = blockIdx.y;
    const float* p = S + ((long)b * LL + l) * KC;
    bf16* d = P + ((long)b * LL + l) * (2 * KC);
    int t = threadIdx.x;
    float v = p[t];
    red[t] = v; __syncthreads();
    for (int o = 32; o > 0; o >>= 1) { if (t < o) red[t] = fmaxf(red[t], red[t + o]); __syncthreads(); }
    float m = red[0]; __syncthreads();
    float e = expf(v - m);
    red[t] = e; __syncthreads();
    for (int o = 32; o > 0; o >>= 1) { if (t < o) red[t] += red[t + o]; __syncthreads(); }
    float val = e / red[0];
    bf16 hh = __float2bfloat16_rn(val);
    d[t]      = hh;
    d[KC + t] = __float2bfloat16_rn(val - __bfloat162float(hh));
}

__global__ void final_kernel(const float* __restrict__ h, const float* __restrict__ fg,
                             const float* __restrict__ fb, const float* __restrict__ wev,
                             const float* __restrict__ bev, float* __restrict__ out) {
    __shared__ float rs[256], rq[256];
    int l = blockIdx.x, b = blockIdx.y;
    const float* xr = h + ((long)b * LL + l) * DD;
    int t = threadIdx.x;
    float v0 = xr[t], v1 = xr[t + 256];
    rs[t] = v0 + v1; rq[t] = v0 * v0 + v1 * v1; __syncthreads();
    for (int o = 128; o > 0; o >>= 1) {
        if (t < o) { rs[t] += rs[t + o]; rq[t] += rq[t + o]; }
        __syncthreads();
    }
    float mean = rs[0] * (1.0f / DD);
    float inv  = rsqrtf(rq[0] * (1.0f / DD) - mean * mean + LN_EPS);
    __syncthreads();
    float d0 = ((v0 - mean) * inv * fg[t]       + fb[t])       * wev[t];
    float d1 = ((v1 - mean) * inv * fg[t + 256] + fb[t + 256]) * wev[t + 256];
    rs[t] = d0 + d1; __syncthreads();
    for (int o = 128; o > 0; o >>= 1) { if (t < o) rs[t] += rs[t + o]; __syncthreads(); }
    if (t == 0) out[b * KC + l] = rs[0] + bev[0];
}

// ---------------------------------------------------------------------------
// bf16x3 GEMM via 3 virtual K-segments over pre-split operands.
// A: (M x 2*KH) [hi|lo] row-major. B:
//   BSTYLE 0: (2*KH x N)  k-major [hi;lo] stacked rows
//   BSTYLE 1: (N x 2*KH)  [hi|lo] row-major (B^T)
// causalKC >= 0: BSTYLE 1 -> skip fully-masked 128x128 score tiles;
//                BSTYLE 0 -> truncate k-loop at the causal diagonal.
// Block 128x128, 8 warps (2x4), warp 64x32, mma m16n8k16 bf16, fp32 accum.
// cp.async 4-stage pipeline, ONE __syncthreads per k-tile.
// ---------------------------------------------------------------------------
__device__ __forceinline__ void mma_bf16(float* c, const unsigned* a, const unsigned* b) {
    asm volatile(
        "mma.sync.aligned.m16n8k16.row.col.f32.bf16.bf16.f32 "
        "{%0,%1,%2,%3}, {%4,%5,%6,%7}, {%8,%9}, {%0,%1,%2,%3};"
        : "+f"(c[0]), "+f"(c[1]), "+f"(c[2]), "+f"(c[3])
        : "r"(a[0]), "r"(a[1]), "r"(a[2]), "r"(a[3]), "r"(b[0]), "r"(b[1]));
}

__device__ __forceinline__ void cpasync16(unsigned daddr, const void* src) {
    asm volatile("cp.async.cg.shared.global [%0], [%1], 16;" :: "r"(daddr), "l"(src));
}

#define ST_BYTES 10240
#define NSTAGE   4

template <int BSTYLE>
__global__ __launch_bounds__(256)
void gemm3(const bf16* __restrict__ A, int lda, long sA,
           const bf16* __restrict__ B, int ldb, long sB,
           int M, int N, int KH, int causalKC,
           float* Cf, int ldcf, long sCf,
           bf16* Chi, bf16* Clo, int ldc2, long sC2,
           const float* __restrict__ bias, float alpha, int flags) {
    const int m0 = blockIdx.y * 128, n0 = blockIdx.x * 128;

    if (BSTYLE == 1 && causalKC >= 0 && m0 >= causalKC && n0 > m0 + 127 - causalKC)
        return;  // fully masked score tile

    int KHlim = KH;
    if (BSTYLE == 0 && causalKC >= 0 && m0 >= causalKC)
        KHlim = min(KH, m0 + 128 - causalKC);   // multiple of 32

    extern __shared__ __align__(16) unsigned char smraw[];
    unsigned aS = (unsigned)__cvta_generic_to_shared(smraw);
    unsigned bS = aS + NSTAGE * ST_BYTES;

    A += (long)blockIdx.z * sA;
    B += (long)blockIdx.z * sB;
    if (Cf)  Cf  += (long)blockIdx.z * sCf;
    if (Chi) { Chi += (long)blockIdx.z * sC2; Clo += (long)blockIdx.z * sC2; }

    const int tid  = threadIdx.x;
    const int lane = tid & 31;
    const int warp = tid >> 5;
    const int wm = (warp >> 2) * 64;
    const int wn = (warp & 3) * 32;
    const int r = lane >> 2, c = lane & 3;

    float acc[4][4][4] = {{{0.f}}};

    const int segs = KHlim >> 5;
    const int KT = segs * 3;

    auto stage = [&](int st, int kt) {
        int sgi = (kt >= segs) + (kt >= 2 * segs);
        int ko = (kt - sgi * segs) << 5;
        int ao = ko + (sgi == 1 ? KH : 0);
        int bo = ko + (sgi == 2 ? KH : 0);
        unsigned ab = aS + st * ST_BYTES;
        unsigned bb = bS + st * ST_BYTES;
        int ch = tid * 2;
#pragma unroll
        for (int i = 0; i < 2; i++) {
            int cc2 = ch + i;
            int row = cc2 >> 2, c16 = cc2 & 3;
            const bf16* src = A + (long)min(m0 + row, M - 1) * lda + ao + c16 * 8;
            cpasync16(ab + row * 80 + c16 * 16, src);
        }
        if (BSTYLE == 1) {
#pragma unroll
            for (int i = 0; i < 2; i++) {
                int cc2 = ch + i;
                int row = cc2 >> 2, c16 = cc2 & 3;
                const bf16* src = B + (long)min(n0 + row, N - 1) * ldb + bo + c16 * 8;
                cpasync16(bb + row * 80 + c16 * 16, src);
            }
        } else {
#pragma unroll
            for (int i = 0; i < 2; i++) {
                int cc2 = ch + i;
                int row = cc2 >> 4, c16 = cc2 & 15;
                int col = min(n0 + c16 * 8, N - 8);
                const bf16* src = B + (long)(bo + row) * ldb + col;
                cpasync16(bb + row * 272 + c16 * 16, src);
            }
        }
    };

    // prologue: 3 stages in flight
    stage(0, 0);
    asm volatile("cp.async.commit_group;");
    if (KT > 1) stage(1, 1);
    asm volatile("cp.async.commit_group;");
    if (KT > 2) stage(2, 2);
    asm volatile("cp.async.commit_group;");

    for (int kt = 0; kt < KT; kt++) {
        asm volatile("cp.async.wait_group 2;");
        __syncthreads();                 // stage kt visible; buffer kt%4 safe to refill
        if (kt + 3 < KT) stage((kt + 3) & (NSTAGE - 1), kt + 3);
        asm volatile("cp.async.commit_group;");

        const int st = kt & (NSTAGE - 1);
        const unsigned ab = aS + st * ST_BYTES;
        const unsigned bb = bS + st * ST_BYTES;
#pragma unroll
        for (int kh = 0; kh < 2; kh++) {
            unsigned a[4][4];
#pragma unroll
            for (int mf = 0; mf < 4; mf++) {
                int row = wm + mf * 16 + (lane & 15);
                unsigned ad = ab + row * 80 + (kh * 2 + (lane >> 4)) * 16;
                asm volatile("ldmatrix.sync.aligned.m8n8.x4.shared.b16 {%0,%1,%2,%3}, [%4];"
                             : "=r"(a[mf][0]), "=r"(a[mf][1]), "=r"(a[mf][2]), "=r"(a[mf][3])
                             : "r"(ad));
            }
            unsigned bfr[4][2];
#pragma unroll
            for (int nfp = 0; nfp < 2; nfp++) {
                int g = lane >> 3, rr2 = lane & 7;
                if (BSTYLE == 1) {
                    int row = wn + nfp * 16 + ((g >> 1) & 1) * 8 + rr2;
                    unsigned ad = bb + row * 80 + (kh * 2 + (g & 1)) * 16;
                    asm volatile("ldmatrix.sync.aligned.m8n8.x4.shared.b16 {%0,%1,%2,%3}, [%4];"
                                 : "=r"(bfr[nfp*2][0]), "=r"(bfr[nfp*2][1]),
                                   "=r"(bfr[nfp*2+1][0]), "=r"(bfr[nfp*2+1][1])
                                 : "r"(ad));
                } else {
                    int row = kh * 16 + (g & 1) * 8 + rr2;
                    int c16 = ((wn + nfp * 16) >> 3) + ((g >> 1) & 1);
                    unsigned ad = bb + row * 272 + c16 * 16;
                    asm volatile("ldmatrix.sync.aligned.m8n8.x4.trans.shared.b16 {%0,%1,%2,%3}, [%4];"
                                 : "=r"(bfr[nfp*2][0]), "=r"(bfr[nfp*2][1]),
                                   "=r"(bfr[nfp*2+1][0]), "=r"(bfr[nfp*2+1][1])
                                 : "r"(ad));
                }
            }
#pragma unroll
            for (int mf = 0; mf < 4; mf++)
#pragma unroll
                for (int nf = 0; nf < 4; nf++)
                    mma_bf16(acc[mf][nf], a[mf], bfr[nf]);
        }
    }

    // ---- epilogue ----
#pragma unroll
    for (int mf = 0; mf < 4; mf++) {
        int r0 = m0 + wm + mf * 16 + r;
#pragma unroll
        for (int nf = 0; nf < 4; nf++) {
            int cc = n0 + wn + nf * 8 + c * 2;
            if (cc < N) {
#pragma unroll
                for (int half = 0; half < 2; half++) {
                    int rr = r0 + half * 8;
                    if (rr < M) {
                        float v0 = alpha * acc[mf][nf][half * 2 + 0];
                        float v1 = alpha * acc[mf][nf][half * 2 + 1];
                        if (bias) { v0 += bias[cc]; v1 += bias[cc + 1]; }
                        if (flags & FLAG_RELU) { v0 = fmaxf(v0, 0.f); v1 = fmaxf(v1, 0.f); }
                        if (Cf) {
                            long base = (long)rr * ldcf + cc;
                            float w0 = v0, w1 = v1;
                            if (flags & FLAG_RES) { w0 += Cf[base]; w1 += Cf[base + 1]; }
                            Cf[base] = w0; Cf[base + 1] = w1;
                        }
                        if (Chi) {
                            long base = (long)rr * ldc2 + cc;
                            bf16 h0 = __float2bfloat16_rn(v0);
                            bf16 h1 = __float2bfloat16_rn(v1);
                            Chi[base]     = h0;
                            Chi[base + 1] = h1;
                            Clo[base]     = __float2bfloat16_rn(v0 - __bfloat162float(h0));
                            Clo[base + 1] = __float2bfloat16_rn(v1 - __bfloat162float(h1));
                        }
                    }
                }
            }
        }
    }
}

// ---------------------------------------------------------------------------
// Host launcher
// ---------------------------------------------------------------------------
static void G3(int bstyle, const bf16* A, int lda, long sA,
               const bf16* B, int ldb, long sB,
               int M, int N, int KH, int causalKC,
               float* Cf, int ldcf, long sCf,
               bf16* Chi, bf16* Clo, int ldc2, long sC2,
               const float* bias, float alpha, int flags) {
    dim3 grid((N + 127) / 128, (M + 127) / 128, BB);
    size_t sh = 2 * NSTAGE * ST_BYTES;
    if (bstyle)
        gemm3<1><<<grid, 256, sh>>>(A, lda, sA, B, ldb, sB, M, N, KH, causalKC,
                                    Cf, ldcf, sCf, Chi, Clo, ldc2, sC2, bias, alpha, flags);
    else
        gemm3<0><<<grid, 256, sh>>>(A, lda, sA, B, ldb, sB, M, N, KH, causalKC,
                                    Cf, ldcf, sCf, Chi, Clo, ldc2, sC2, bias, alpha, flags);
}

extern "C" void kernel_launch(void* const* d_in, const int* in_sizes, int n_in,
                              void* d_out, int out_size) {
    const int*   cache = (const int*)d_in[0];
    const int*   seq   = (const int*)d_in[1];
    const float* item  = (const float*)d_in[2];
    const float* cpos  = (const float*)d_in[3];
    const float* spos  = (const float*)d_in[4];
    const float* seg   = (const float*)d_in[5];
    const float* wq_s  = (const float*)d_in[6];
    const float* wk_s  = (const float*)d_in[7];
    const float* wv_s  = (const float*)d_in[8];
    const float* wq_c  = (const float*)d_in[9];
    const float* wk_c  = (const float*)d_in[10];
    const float* wv_c  = (const float*)d_in[11];
    const float* w_out = (const float*)d_in[12];
    const float* b_out = (const float*)d_in[13];
    const float* ln1g  = (const float*)d_in[14];
    const float* ln1b  = (const float*)d_in[15];
    const float* ln2g  = (const float*)d_in[16];
    const float* ln2b  = (const float*)d_in[17];
    const float* wff1  = (const float*)d_in[18];
    const float* bff1  = (const float*)d_in[19];
    const float* wff2  = (const float*)d_in[20];
    const float* bff2  = (const float*)d_in[21];
    const float* fing  = (const float*)d_in[22];
    const float* finb  = (const float*)d_in[23];
    const float* wev   = (const float*)d_in[24];
    const float* bev   = (const float*)d_in[25];
    float* out = (float*)d_out;

    cudaFuncSetAttribute(gemm3<0>, cudaFuncAttributeMaxDynamicSharedMemorySize, 2 * NSTAGE * ST_BYTES);
    cudaFuncSetAttribute(gemm3<1>, cudaFuncAttributeMaxDynamicSharedMemorySize, 2 * NSTAGE * ST_BYTES);

    float *h, *s;
    bf16 *hn2, *q2, *k2, *v2, *kc2, *vc2, *p2, *pc2, *cat2, *w2;
    cudaGetSymbolAddress((void**)&h,   g_h);
    cudaGetSymbolAddress((void**)&s,   g_s);
    cudaGetSymbolAddress((void**)&hn2, g_hn2);
    cudaGetSymbolAddress((void**)&q2,  g_q2);
    cudaGetSymbolAddress((void**)&k2,  g_k2);
    cudaGetSymbolAddress((void**)&v2,  g_v2);
    cudaGetSymbolAddress((void**)&kc2, g_kc2);
    cudaGetSymbolAddress((void**)&vc2, g_vc2);
    cudaGetSymbolAddress((void**)&p2,  g_p2);
    cudaGetSymbolAddress((void**)&pc2, g_pc2);
    cudaGetSymbolAddress((void**)&cat2,g_cat2);
    cudaGetSymbolAddress((void**)&w2,  g_w2);

    const float scale = 0.0625f;   // 1/sqrt(256)

    // ---- split all weights (stacked [hi;lo]) ----
    for (int l = 0; l < NLL; l++) {
        bf16* wb = w2 + l * WL;
        auto SPL = [&](const float* src, bf16* dst, long els) {
            split_kernel<<<(unsigned)((els + 255) / 256), 256>>>(src, dst, dst + els, els);
        };
        SPL(wq_s + (long)l * DD * DHH,  wb + OQ,   (long)DD * DHH);
        SPL(wk_s + (long)l * DD * DHH,  wb + OK_,  (long)DD * DHH);
        SPL(wv_s + (long)l * DD * DHH,  wb + OV,   (long)DD * DHH);
        SPL(wq_c + (long)l * DD * DHH,  wb + OQC,  (long)DD * DHH);
        SPL(wk_c + (long)l * DD * DHH,  wb + OKCo, (long)DD * DHH);
        SPL(wv_c + (long)l * DD * DHH,  wb + OVC,  (long)DD * DHH);
        SPL(w_out + (long)l * DD * DD,  wb + OWO,  (long)DD * DD);
        SPL(wff1 + (long)l * DD * DFFF, wb + OF1,  (long)DD * DFFF);
        SPL(wff2 + (long)l * DFFF * DD, wb + OF2,  (long)DFFF * DD);
    }

    embed_kernel<<<BB * LL, 256>>>(cache, seq, item, cpos, spos, seg, h);

    for (int l = 0; l < NLL; l++) {
        bf16* wb = w2 + l * WL;
        const float* Bo = b_out + (long)l * DD;
        const float* B1 = bff1 + (long)l * DFFF;
        const float* B2 = bff2 + (long)l * DD;

        const int Mq = (l == NLL - 1) ? KC : LL;

        // ---- LN1 (all rows: K/V need them) ----
        ln_split_kernel<<<dim3(LL, BB), 256>>>(h, hn2, ln1g + l * DD, ln1b + l * DD);

        // ---- Attention A (seq keys, causal) ----
        G3(0, hn2, 2*DD, (long)LL*2*DD, wb + OQ, DHH, 0, Mq, DHH, DD, -1,
           0, 0, 0, q2, q2 + DHH, 2*DHH, (long)LL*2*DHH, 0, 1.f, 0);
        G3(0, hn2 + (long)KC*2*DD, 2*DD, (long)LL*2*DD, wb + OK_, DHH, 0, WW, DHH, DD, -1,
           0, 0, 0, k2, k2 + DHH, 2*DHH, (long)WW*2*DHH, 0, 1.f, 0);
        G3(0, hn2 + (long)KC*2*DD, 2*DD, (long)LL*2*DD, wb + OV, DHH, 0, WW, DHH, DD, -1,
           0, 0, 0, v2, v2 + (long)WW*DHH, DHH, (long)2*WW*DHH, 0, 1.f, 0);
        G3(1, q2, 2*DHH, (long)LL*2*DHH, k2, 2*DHH, (long)WW*2*DHH, Mq, WW, DHH, KC,
           s, WW, (long)LL*WW, 0, 0, 0, 0, 0, scale, 0);
        softmax_seq_kernel<<<dim3(Mq, BB), 512>>>(s, p2);
        G3(0, p2, 2*WW, (long)LL*2*WW, v2, DHH, (long)2*WW*DHH, Mq, DHH, WW, KC,
           0, 0, 0, cat2, cat2 + DD, 2*DD, (long)LL*2*DD, 0, 1.f, 0);

        // ---- Attention B (cache keys) ----
        G3(0, hn2, 2*DD, (long)LL*2*DD, wb + OQC, DHH, 0, Mq, DHH, DD, -1,
           0, 0, 0, q2, q2 + DHH, 2*DHH, (long)LL*2*DHH, 0, 1.f, 0);
        G3(0, hn2, 2*DD, (long)LL*2*DD, wb + OKCo, DHH, 0, KC, DHH, DD, -1,
           0, 0, 0, kc2, kc2 + DHH, 2*DHH, (long)KC*2*DHH, 0, 1.f, 0);
        G3(0, hn2, 2*DD, (long)LL*2*DD, wb + OVC, DHH, 0, KC, DHH, DD, -1,
           0, 0, 0, vc2, vc2 + (long)KC*DHH, DHH, (long)2*KC*DHH, 0, 1.f, 0);
        G3(1, q2, 2*DHH, (long)LL*2*DHH, kc2, 2*DHH, (long)KC*2*DHH, Mq, KC, DHH, -1,
           s, KC, (long)LL*KC, 0, 0, 0, 0, 0, scale, 0);
        softmax_cache_kernel<<<dim3(Mq, BB), 64>>>(s, pc2);
        G3(0, pc2, 2*KC, (long)LL*2*KC, vc2, DHH, (long)2*KC*DHH, Mq, DHH, KC, -1,
           0, 0, 0, cat2 + DHH, cat2 + DD + DHH, 2*DD, (long)LL*2*DD, 0, 1.f, 0);

        // ---- Output projection + residual ----
        G3(0, cat2, 2*DD, (long)LL*2*DD, wb + OWO, DD, 0, Mq, DD, DD, -1,
           h, DD, (long)LL*DD, 0, 0, 0, 0, Bo, 1.f, FLAG_RES);

        // ---- FFN ----
        ln_split_kernel<<<dim3(Mq, BB), 256>>>(h, hn2, ln2g + l * DD, ln2b + l * DD);
        G3(0, hn2, 2*DD, (long)LL*2*DD, wb + OF1, DFFF, 0, Mq, DFFF, DD, -1,
           0, 0, 0, p2, p2 + DFFF, 2*DFFF, (long)LL*2*DFFF, B1, 1.f, FLAG_RELU);
        G3(0, p2, 2*DFFF, (long)LL*2*DFFF, wb + OF2, DD, 0, Mq, DD, DFFF, -1,
           h, DD, (long)LL*DD, 0, 0, 0, 0, B2, 1.f, FLAG_RES);
    }

    final_kernel<<<dim3(KC, BB), 256>>>(h, fing, finb, wev, bev, out);
}